// round 4
// baseline (speedup 1.0000x reference)
#include <cuda_runtime.h>

// Problem constants
#define BB   2
#define NN   2048
#define NTT  8
#define HHH  64
#define WWW  64
#define DXC  3
#define DZC  16
#define GG   (NTT*HHH*WWW)        // 32768
#define XG_SZ (BB*GG*DXC)         // 196608
#define ZG_SZ (BB*GG*DZC)         // 1048576

#define NC     128                // n-tile
#define LOG2E  1.4426950408889634f

// precomputed w-direction kernel, pair-packed: (ww[n][j], ww[n][j+32])
__device__ unsigned long long d_wwpair[BB * NN * 32];   // 1 MB

// ---------- packed f32x2 helpers ----------
__device__ __forceinline__ unsigned long long pack2(float v) {
    unsigned long long r;
    asm("mov.b64 %0, {%1, %1};" : "=l"(r) : "f"(v));
    return r;
}
__device__ __forceinline__ unsigned long long pack2d(float a, float b) {
    unsigned long long r;
    asm("mov.b64 %0, {%1, %2};" : "=l"(r) : "f"(a), "f"(b));
    return r;
}
__device__ __forceinline__ void unpack2(float& a, float& b, unsigned long long v) {
    asm("mov.b64 {%0, %1}, %2;" : "=f"(a), "=f"(b) : "l"(v));
}
__device__ __forceinline__ unsigned long long fma2(unsigned long long a,
                                                   unsigned long long b,
                                                   unsigned long long c) {
    unsigned long long d;
    asm("fma.rn.f32x2 %0, %1, %2, %3;" : "=l"(d) : "l"(a), "l"(b), "l"(c));
    return d;
}
__device__ __forceinline__ float ex2(float x) {
    float y;
    asm("ex2.approx.ftz.f32 %0, %1;" : "=f"(y) : "f"(x));
    return y;
}

__device__ __forceinline__ float inv_ls(const float* lsp, int d) {
    float p  = lsp[d];
    float ls = 1e-5f + log1pf(__expf(p));
    return 1.0f / ls;
}

// ---------- x_grid ----------
__global__ void xgrid_kernel(const float* __restrict__ tg, float* __restrict__ out) {
    int idx = blockIdx.x * blockDim.x + threadIdx.x;
    if (idx >= XG_SZ) return;
    int d = idx % DXC;
    int p = idx / DXC;
    int w = p % WWW; p /= WWW;
    int h = p % HHH; p /= HHH;
    int t = p % NTT;
    int b = p / NTT;
    float v;
    if (d == 0)      v = tg[b * NTT + t];
    else if (d == 1) v = -1.0f + (2.0f / (HHH - 1)) * (float)h;
    else             v = -1.0f + (2.0f / (WWW - 1)) * (float)w;
    out[idx] = v;
}

// ---------- pre-kernel: ww[b][n][w] = exp2(-0.5*L*((Wv - x2)/ls2)^2), pair-packed ----------
__global__ void wwtab_kernel(const float* __restrict__ x, const float* __restrict__ lsp) {
    int idx = blockIdx.x * blockDim.x + threadIdx.x;   // BB*NN*32
    if (idx >= BB * NN * 32) return;
    int j = idx & 31;
    int n = (idx >> 5) & (NN - 1);
    int b = idx >> 16;                                  // NN*32 = 65536
    float inv2 = inv_ls(lsp, 2);
    float c2 = x[(b * NN + n) * 3 + 2] * inv2;
    float w0v = (-1.0f + (2.0f / 63.0f) * (float)j)        * inv2;
    float w1v = (-1.0f + (2.0f / 63.0f) * (float)(j + 32)) * inv2;
    float d0 = w0v - c2, d1 = w1v - c2;
    float e0 = ex2(-0.5f * LOG2E * d0 * d0);
    float e1 = ex2(-0.5f * LOG2E * d1 * d1);
    d_wwpair[idx] = pack2d(e0, e1);
}

// ---------- z_grid ----------
// 1 warp per block, 128 grid points: (t, h0=2hp, h1=2hp+1) x w=0..63.
// Lane owns w=lane and w=lane+32 in both h-rows.
// weight(g,n) = s_row[n] * ww[n][w]; s_row[n] = exp(t,h part) per-warp table.
__global__ __launch_bounds__(32)
void zgrid_kernel(const float* __restrict__ x, const float* __restrict__ z,
                  const float* __restrict__ tg, const float* __restrict__ lsp,
                  float* __restrict__ out) {
    __shared__ float s0[NN];                    // 8 KB  (t,h0) factor
    __shared__ float s1[NN];                    // 8 KB  (t,h1) factor
    __shared__ unsigned long long s_ww[NC * 32];// 32 KB ww pair tile
    __shared__ ulonglong2 s_z[NC * 4];          // 8 KB  z tile

    const int lane = threadIdx.x;
    const int blk  = blockIdx.x;               // 512 blocks
    const int b    = blk >> 8;
    const int r    = blk & 255;
    const int t    = r >> 5;
    const int hp   = r & 31;
    const int h0   = hp * 2;
    const int h1   = h0 + 1;

    const float inv0 = inv_ls(lsp, 0);
    const float inv1 = inv_ls(lsp, 1);

    const float tv  = tg[b * NTT + t] * inv0;
    const float hv0 = (-1.0f + (2.0f / 63.0f) * (float)h0) * inv1;
    const float hv1 = (-1.0f + (2.0f / 63.0f) * (float)h1) * inv1;

    const float* xb = x + (size_t)b * NN * DXC;

    // per-warp (t,h) factor tables
    for (int n = lane; n < NN; n += 32) {
        float c0 = xb[n * 3 + 0] * inv0;
        float c1 = xb[n * 3 + 1] * inv1;
        float dt = tv - c0;
        float d0 = hv0 - c1;
        float d1 = hv1 - c1;
        s0[n] = ex2(-0.5f * LOG2E * (dt * dt + d0 * d0));
        s1[n] = ex2(-0.5f * LOG2E * (dt * dt + d1 * d1));
    }

    unsigned long long a00[8], a01[8], a10[8], a11[8];
#pragma unroll
    for (int i = 0; i < 8; i++) { a00[i]=0ull; a01[i]=0ull; a10[i]=0ull; a11[i]=0ull; }

    const ulonglong2* zb = (const ulonglong2*)(z + (size_t)b * NN * DZC);
    const ulonglong2* wwsrc = (const ulonglong2*)(d_wwpair + (size_t)b * NN * 32);

    for (int n0 = 0; n0 < NN; n0 += NC) {
        __syncthreads();
        // stage ww pair tile (NC*16 ulonglong2)
        for (int i = lane; i < NC * 16; i += 32)
            ((ulonglong2*)s_ww)[i] = wwsrc[(size_t)n0 * 16 + i];
        // stage z tile
        for (int i = lane; i < NC * 4; i += 32)
            s_z[i] = zb[(size_t)n0 * 4 + i];
        __syncthreads();

#pragma unroll 2
        for (int nl = 0; nl < NC; nl++) {
            unsigned long long wwp = s_ww[nl * 32 + lane];
            float wlo, whi; unpack2(wlo, whi, wwp);
            float sa = s0[n0 + nl];
            float sb = s1[n0 + nl];
            unsigned long long w00 = pack2(sa * wlo);
            unsigned long long w01 = pack2(sa * whi);
            unsigned long long w10 = pack2(sb * wlo);
            unsigned long long w11 = pack2(sb * whi);
            ulonglong2 z0 = s_z[nl * 4 + 0];
            ulonglong2 z1 = s_z[nl * 4 + 1];
            ulonglong2 z2 = s_z[nl * 4 + 2];
            ulonglong2 z3 = s_z[nl * 4 + 3];
            a00[0]=fma2(z0.x,w00,a00[0]); a00[1]=fma2(z0.y,w00,a00[1]);
            a00[2]=fma2(z1.x,w00,a00[2]); a00[3]=fma2(z1.y,w00,a00[3]);
            a00[4]=fma2(z2.x,w00,a00[4]); a00[5]=fma2(z2.y,w00,a00[5]);
            a00[6]=fma2(z3.x,w00,a00[6]); a00[7]=fma2(z3.y,w00,a00[7]);
            a01[0]=fma2(z0.x,w01,a01[0]); a01[1]=fma2(z0.y,w01,a01[1]);
            a01[2]=fma2(z1.x,w01,a01[2]); a01[3]=fma2(z1.y,w01,a01[3]);
            a01[4]=fma2(z2.x,w01,a01[4]); a01[5]=fma2(z2.y,w01,a01[5]);
            a01[6]=fma2(z3.x,w01,a01[6]); a01[7]=fma2(z3.y,w01,a01[7]);
            a10[0]=fma2(z0.x,w10,a10[0]); a10[1]=fma2(z0.y,w10,a10[1]);
            a10[2]=fma2(z1.x,w10,a10[2]); a10[3]=fma2(z1.y,w10,a10[3]);
            a10[4]=fma2(z2.x,w10,a10[4]); a10[5]=fma2(z2.y,w10,a10[5]);
            a10[6]=fma2(z3.x,w10,a10[6]); a10[7]=fma2(z3.y,w10,a10[7]);
            a11[0]=fma2(z0.x,w11,a11[0]); a11[1]=fma2(z0.y,w11,a11[1]);
            a11[2]=fma2(z1.x,w11,a11[2]); a11[3]=fma2(z1.y,w11,a11[3]);
            a11[4]=fma2(z2.x,w11,a11[4]); a11[5]=fma2(z2.y,w11,a11[5]);
            a11[6]=fma2(z3.x,w11,a11[6]); a11[7]=fma2(z3.y,w11,a11[7]);
        }
    }

    // stores: 4 grid points x 4 STG.128
    const size_t gb = (size_t)((b * NTT + t) * HHH) * WWW;
    ulonglong2* o;
    o = (ulonglong2*)out + (gb + (size_t)h0 * WWW + lane) * 4;
    o[0]=make_ulonglong2(a00[0],a00[1]); o[1]=make_ulonglong2(a00[2],a00[3]);
    o[2]=make_ulonglong2(a00[4],a00[5]); o[3]=make_ulonglong2(a00[6],a00[7]);
    o = (ulonglong2*)out + (gb + (size_t)h0 * WWW + lane + 32) * 4;
    o[0]=make_ulonglong2(a01[0],a01[1]); o[1]=make_ulonglong2(a01[2],a01[3]);
    o[2]=make_ulonglong2(a01[4],a01[5]); o[3]=make_ulonglong2(a01[6],a01[7]);
    o = (ulonglong2*)out + (gb + (size_t)h1 * WWW + lane) * 4;
    o[0]=make_ulonglong2(a10[0],a10[1]); o[1]=make_ulonglong2(a10[2],a10[3]);
    o[2]=make_ulonglong2(a10[4],a10[5]); o[3]=make_ulonglong2(a10[6],a10[7]);
    o = (ulonglong2*)out + (gb + (size_t)h1 * WWW + lane + 32) * 4;
    o[0]=make_ulonglong2(a11[0],a11[1]); o[1]=make_ulonglong2(a11[2],a11[3]);
    o[2]=make_ulonglong2(a11[4],a11[5]); o[3]=make_ulonglong2(a11[6],a11[7]);
}

extern "C" void kernel_launch(void* const* d_in, const int* in_sizes, int n_in,
                              void* d_out, int out_size) {
    const float* x   = (const float*)d_in[0];
    const float* z   = (const float*)d_in[1];
    const float* tg  = (const float*)d_in[2];
    const float* lsp = (const float*)d_in[3];
    float* out = (float*)d_out;

    float* xg = nullptr;
    float* zg = nullptr;
    if (out_size == XG_SZ + ZG_SZ)      { xg = out; zg = out + XG_SZ; }
    else if (out_size == ZG_SZ)         { zg = out; }
    else if (out_size == XG_SZ)         { xg = out; }
    else                                { xg = out; zg = out + XG_SZ; }

    if (xg) xgrid_kernel<<<(XG_SZ + 255) / 256, 256>>>(tg, xg);
    if (zg) {
        wwtab_kernel<<<(BB * NN * 32 + 255) / 256, 256>>>(x, lsp);
        zgrid_kernel<<<BB * GG / 128, 32>>>(x, z, tg, lsp, zg);
    }
}

// round 9
// speedup vs baseline: 3.1277x; 3.1277x over previous
#include <cuda_runtime.h>
#include <cuda_bf16.h>
#include <cstdint>

// Problem constants
#define BB   2
#define NN   2048
#define NTT  8
#define HHH  64
#define WWW  64
#define DXC  3
#define DZC  16
#define GG   (NTT*HHH*WWW)
#define XG_SZ (BB*GG*DXC)         // 196608
#define ZG_SZ (BB*GG*DZC)         // 1048576
#define LOG2E 1.4426950408889634f

// ---- precomputed tables (global scratch) ----
__device__ float          g_ww[BB * WWW * NN];        // 2 MB  w-factor  [b][w][n]
__device__ float          g_sh[BB * HHH * NN];        // 2 MB  h-factor  [b][h][n]
// z_t tables, layout [b*2+tgrp][col=tloc*16+e][n'], n' permuted for B-fragment LDS.64
__device__ __nv_bfloat16  g_zti_hi[BB * 2 * 64 * NN]; // 1 MB
__device__ __nv_bfloat16  g_zti_lo[BB * 2 * 64 * NN]; // 1 MB

// ---------- helpers ----------
__device__ __forceinline__ float ex2(float x) {
    float y; asm("ex2.approx.ftz.f32 %0, %1;" : "=f"(y) : "f"(x)); return y;
}
__device__ __forceinline__ float inv_ls(const float* lsp, int d) {
    float p = lsp[d];
    return 1.0f / (1e-5f + log1pf(__expf(p)));
}
__device__ __forceinline__ uint32_t smem_u32(const void* p) {
    uint32_t a;
    asm("{ .reg .u64 t; cvta.to.shared.u64 t, %1; cvt.u32.u64 %0, t; }" : "=r"(a) : "l"(p));
    return a;
}
__device__ __forceinline__ void cp_async16(uint32_t dst, const void* src) {
    asm volatile("cp.async.cg.shared.global [%0], [%1], 16;" :: "r"(dst), "l"(src));
}
__device__ __forceinline__ void cp_commit() { asm volatile("cp.async.commit_group;" ::: "memory"); }

// cvt two f32 -> packed bf16x2 (first operand = HIGH half)
__device__ __forceinline__ uint32_t cvt_bf2(float hi, float lo) {
    uint32_t r; asm("cvt.rn.bf16x2.f32 %0, %1, %2;" : "=r"(r) : "f"(hi), "f"(lo)); return r;
}
// split pair (f0 -> low lane, f1 -> high lane) into bf16 hi + residual lo
__device__ __forceinline__ void split2(float f0, float f1, uint32_t& hi, uint32_t& lo) {
    hi = cvt_bf2(f1, f0);
    float h0 = __uint_as_float(hi << 16);
    float h1 = __uint_as_float(hi & 0xffff0000u);
    lo = cvt_bf2(f1 - h1, f0 - h0);
}
__device__ __forceinline__ void mma16816(float* c, uint32_t a0, uint32_t a1,
                                         uint32_t a2, uint32_t a3,
                                         uint32_t b0, uint32_t b1) {
    asm volatile(
        "mma.sync.aligned.m16n8k16.row.col.f32.bf16.bf16.f32 "
        "{%0,%1,%2,%3}, {%4,%5,%6,%7}, {%8,%9}, {%0,%1,%2,%3};"
        : "+f"(c[0]), "+f"(c[1]), "+f"(c[2]), "+f"(c[3])
        : "r"(a0), "r"(a1), "r"(a2), "r"(a3), "r"(b0), "r"(b1));
}

// ---------- x_grid ----------
__global__ void xgrid_kernel(const float* __restrict__ tg, float* __restrict__ out) {
    int idx = blockIdx.x * blockDim.x + threadIdx.x;
    if (idx >= XG_SZ) return;
    int d = idx % DXC;
    int p = idx / DXC;
    int w = p % WWW; p /= WWW;
    int h = p % HHH; p /= HHH;
    int t = p % NTT;
    int b = p / NTT;
    float v;
    if (d == 0)      v = tg[b * NTT + t];
    else if (d == 1) v = -1.0f + (2.0f / 63.0f) * (float)h;
    else             v = -1.0f + (2.0f / 63.0f) * (float)w;
    out[idx] = v;
}

// ---------- pre: ww and sh factor tables ----------
__global__ void wwsh_kernel(const float* __restrict__ x, const float* __restrict__ lsp) {
    int idx = blockIdx.x * blockDim.x + threadIdx.x;   // 2 tables * 2b * 64 * 2048
    if (idx >= 2 * BB * 64 * NN) return;
    int n   = idx & (NN - 1);
    int r   = (idx >> 11) & 63;
    int b   = (idx >> 17) & 1;
    int tab = idx >> 18;
    int dim = tab ? 1 : 2;                             // tab0 = ww (coord 2), tab1 = sh (coord 1)
    float inv = inv_ls(lsp, dim);
    float c   = x[(b * NN + n) * 3 + dim] * inv;
    float gv  = (-1.0f + (2.0f / 63.0f) * (float)r) * inv;
    float d   = gv - c;
    float e   = ex2(-0.5f * LOG2E * d * d);
    if (tab == 0) g_ww[((size_t)b * 64 + r) * NN + n] = e;
    else          g_sh[((size_t)b * 64 + r) * NN + n] = e;
}

// ---------- pre: z_t = st*z, bf16 hi/lo, permuted for B fragments ----------
__global__ void zt_kernel(const float* __restrict__ x, const float* __restrict__ z,
                          const float* __restrict__ tg, const float* __restrict__ lsp) {
    int idx = blockIdx.x * blockDim.x + threadIdx.x;   // 2*8*16*2048 = 2^19
    if (idx >= BB * NTT * DZC * NN) return;
    int n = idx & (NN - 1);
    int e = (idx >> 11) & 15;
    int t = (idx >> 15) & 7;
    int b = idx >> 18;
    float inv0 = inv_ls(lsp, 0);
    float tv = tg[b * NTT + t] * inv0;
    float c0 = x[(b * NN + n) * 3 + 0] * inv0;
    float d  = tv - c0;
    float st = ex2(-0.5f * LOG2E * d * d);
    float v  = st * z[(b * NN + n) * DZC + e];
    __nv_bfloat16 hi = __float2bfloat16_rn(v);
    float vlo = v - __bfloat162float(hi);
    // B-fragment permutation within each 16-n group: word-pair wp -> position
    int wp  = (n >> 1) & 7;
    int pos = (wp < 4) ? (wp * 2) : ((wp - 4) * 2 + 1);
    int np  = (n & ~15) | (pos << 1) | (n & 1);
    int tgrp = t >> 2, tloc = t & 3;
    int col  = tloc * 16 + e;
    size_t o = ((size_t)(b * 2 + tgrp) * 64 + col) * NN + np;
    g_zti_hi[o] = hi;
    g_zti_lo[o] = __float2bfloat16_rn(vlo);
}

// ---------- main HMMA kernel ----------
// CTA(bid): b, tgrp, hpair. D[128 x 64] = A[128,2048] * B[64,2048]^T.
// A row m = hl*64 + w : weight ww[b][w][n]*sh[b][h0+hl][n], generated in-register,
//   split into bf16 hi + lo. B row col = tloc*16+e : z_t hi/lo tables.
// 3 products: Ahi*Bhi + Ahi*Blo + Alo*Bhi.
#define KC      64
#define NCH     (NN / KC)          // 32
#define ZTHI_O  0
#define ZTLO_O  8192
#define WW_O    16384
#define SH_O    32768
#define BUFSZ   33280
#define SMEM_T  (2 * BUFSZ)        // 66560

__global__ __launch_bounds__(256, 1)
void zgrid_mma_kernel(float* __restrict__ out) {
    extern __shared__ char smem[];
    const uint32_t sb = smem_u32(smem);
    const int tid  = threadIdx.x;
    const int wid  = tid >> 5;
    const int lane = tid & 31;

    const int bid   = blockIdx.x;           // 128
    const int hpair = bid & 31;
    const int tgrp  = (bid >> 5) & 1;
    const int b     = bid >> 6;
    const int h0    = hpair * 2;
    const int b2    = b * 2 + tgrp;

    const int mbase = (wid & 3) * 32;       // warp row block
    const int colg  = (wid >> 2) * 32;      // warp col block
    const int mloc  = mbase & 63;           // w-row base within ww tile
    const int hl    = mbase >> 6;           // 0 or 1
    const int q8    = (lane & 3) * 8;
    const int lr    = lane >> 2;

    float acc[2][4][4];
#pragma unroll
    for (int i = 0; i < 2; i++)
#pragma unroll
        for (int j = 0; j < 4; j++)
#pragma unroll
            for (int k = 0; k < 4; k++) acc[i][j][k] = 0.0f;

    // ---- stage one chunk into buffer ----
    auto stage = [&](int ch) {
        const uint32_t ba = sb + (ch & 1) * BUFSZ;
        // zt hi+lo: 64 cols x 8 chunks x 2 comps = 1024 x 16B
        for (int i = tid; i < 1024; i += 256) {
            int comp = i >> 9;                     // 0 = hi, 1 = lo
            int r    = i & 511;
            int col  = r >> 3, c = r & 7;          // col 0..63, chunk 0..7
            const __nv_bfloat16* src =
                (comp ? g_zti_lo : g_zti_hi) + ((size_t)b2 * 64 + col) * NN + ch * KC + c * 8;
            uint32_t dst = ba + (comp ? ZTLO_O : ZTHI_O)
                         + col * 128 + (((c >> 1) + col) & 3) * 32 + (c & 1) * 16;
            cp_async16(dst, src);
        }
        // ww: 64 rows x 16 chunks = 1024 x 16B
        for (int i = tid; i < 1024; i += 256) {
            int w = i >> 4, c = i & 15;
            const float* src = g_ww + ((size_t)b * 64 + w) * NN + ch * KC + c * 4;
            uint32_t dst = ba + WW_O + w * 256 + (((c >> 1) + w) & 7) * 32 + (c & 1) * 16;
            cp_async16(dst, src);
        }
        // sh: 2 rows x 16 x 16B
        if (tid < 32) {
            int j = tid >> 4, c = tid & 15;
            const float* src = g_sh + ((size_t)b * 64 + h0 + j) * NN + ch * KC + c * 4;
            uint32_t dst = ba + SH_O + j * 256 + c * 16;
            cp_async16(dst, src);
        }
        cp_commit();
    };

    stage(0);

    for (int ch = 0; ch < NCH; ch++) {
        if (ch + 1 < NCH) {
            stage(ch + 1);
            asm volatile("cp.async.wait_group 1;" ::: "memory");
        } else {
            asm volatile("cp.async.wait_group 0;" ::: "memory");
        }
        __syncthreads();

        const char* buf = smem + (ch & 1) * BUFSZ;

#pragma unroll
        for (int ks = 0; ks < 4; ks++) {
            // sh pairs (broadcast)
            float2 sl = *(const float2*)(buf + SH_O + hl * 256 + ks * 64 + q8);
            float2 sh = *(const float2*)(buf + SH_O + hl * 256 + ks * 64 + 32 + q8);

            uint32_t ahi[2][4], alo[2][4];
#pragma unroll
            for (int mf = 0; mf < 2; mf++) {
                int r0 = mloc + mf * 16 + lr;
                int r1 = r0 + 8;
                float2 w0l = *(const float2*)(buf + WW_O + r0 * 256 + (((2 * ks)     + r0) & 7) * 32 + q8);
                float2 w0h = *(const float2*)(buf + WW_O + r0 * 256 + (((2 * ks + 1) + r0) & 7) * 32 + q8);
                float2 w1l = *(const float2*)(buf + WW_O + r1 * 256 + (((2 * ks)     + r1) & 7) * 32 + q8);
                float2 w1h = *(const float2*)(buf + WW_O + r1 * 256 + (((2 * ks + 1) + r1) & 7) * 32 + q8);
                split2(w0l.x * sl.x, w0l.y * sl.y, ahi[mf][0], alo[mf][0]);  // (r0, klo)
                split2(w1l.x * sl.x, w1l.y * sl.y, ahi[mf][1], alo[mf][1]);  // (r1, klo)
                split2(w0h.x * sh.x, w0h.y * sh.y, ahi[mf][2], alo[mf][2]);  // (r0, khi)
                split2(w1h.x * sh.x, w1h.y * sh.y, ahi[mf][3], alo[mf][3]);  // (r1, khi)
            }

#pragma unroll
            for (int nt = 0; nt < 4; nt++) {
                int col = colg + nt * 8 + lr;
                int off = col * 128 + ((ks + col) & 3) * 32 + q8;
                uint2 bh = *(const uint2*)(buf + ZTHI_O + off);
                uint2 bl = *(const uint2*)(buf + ZTLO_O + off);
#pragma unroll
                for (int mf = 0; mf < 2; mf++) {
                    mma16816(acc[mf][nt], ahi[mf][0], ahi[mf][1], ahi[mf][2], ahi[mf][3], bh.x, bh.y);
                    mma16816(acc[mf][nt], ahi[mf][0], ahi[mf][1], ahi[mf][2], ahi[mf][3], bl.x, bl.y);
                    mma16816(acc[mf][nt], alo[mf][0], alo[mf][1], alo[mf][2], alo[mf][3], bh.x, bh.y);
                }
            }
        }
        __syncthreads();
    }

    // ---- epilogue ----
#pragma unroll
    for (int mf = 0; mf < 2; mf++) {
#pragma unroll
        for (int nt = 0; nt < 4; nt++) {
            int m0    = mbase + mf * 16 + lr;       // 0..127
            int cbase = colg + nt * 8 + (lane & 3) * 2;
            int tloc  = cbase >> 4;
            int e     = cbase & 15;
            int t     = tgrp * 4 + tloc;
            int h     = h0 + (m0 >> 6);
            int w0    = m0 & 63;
            size_t i0 = (((size_t)(b * NTT + t) * HHH + h) * WWW + w0) * DZC + e;
            *(float2*)(out + i0) = make_float2(acc[mf][nt][0], acc[mf][nt][1]);
            size_t i1 = i0 + 8 * DZC;               // row m0+8 -> w0+8 (same h)
            *(float2*)(out + i1) = make_float2(acc[mf][nt][2], acc[mf][nt][3]);
        }
    }
}

extern "C" void kernel_launch(void* const* d_in, const int* in_sizes, int n_in,
                              void* d_out, int out_size) {
    const float* x   = (const float*)d_in[0];
    const float* z   = (const float*)d_in[1];
    const float* tg  = (const float*)d_in[2];
    const float* lsp = (const float*)d_in[3];
    float* out = (float*)d_out;

    float* xg = nullptr;
    float* zg = nullptr;
    if (out_size == XG_SZ + ZG_SZ)      { xg = out; zg = out + XG_SZ; }
    else if (out_size == ZG_SZ)         { zg = out; }
    else if (out_size == XG_SZ)         { xg = out; }
    else                                { xg = out; zg = out + XG_SZ; }

    if (xg) xgrid_kernel<<<(XG_SZ + 255) / 256, 256>>>(tg, xg);
    if (zg) {
        cudaFuncSetAttribute(zgrid_mma_kernel,
                             cudaFuncAttributeMaxDynamicSharedMemorySize, SMEM_T);
        wwsh_kernel<<<(2 * BB * 64 * NN + 255) / 256, 256>>>(x, lsp);
        zt_kernel<<<(BB * NTT * DZC * NN + 255) / 256, 256>>>(x, z, tg, lsp);
        zgrid_mma_kernel<<<BB * 2 * 32, 256, SMEM_T>>>(zg);
    }
}

// round 10
// speedup vs baseline: 3.3250x; 1.0631x over previous
#include <cuda_runtime.h>
#include <cuda_bf16.h>
#include <cstdint>

// Problem constants
#define BB   2
#define NN   2048
#define NTT  8
#define HHH  64
#define WWW  64
#define DXC  3
#define DZC  16
#define GG   (NTT*HHH*WWW)
#define XG_SZ (BB*GG*DXC)         // 196608
#define ZG_SZ (BB*GG*DZC)         // 1048576
#define LOG2E 1.4426950408889634f

// ---- precomputed tables (global scratch) ----
__device__ float          g_ww[BB * WWW * NN];        // 2 MB  w-factor  [b][w][n]
__device__ float          g_sh[BB * HHH * NN];        // 2 MB  h-factor  [b][h][n]
// z_t tables, layout [b*4+tgrp][col=tloc*16+e][n'], n' permuted for B-fragment LDS.64
__device__ __nv_bfloat16  g_zti_hi[BB * 4 * 32 * NN]; // 1 MB
__device__ __nv_bfloat16  g_zti_lo[BB * 4 * 32 * NN]; // 1 MB

// ---------- helpers ----------
__device__ __forceinline__ float ex2(float x) {
    float y; asm("ex2.approx.ftz.f32 %0, %1;" : "=f"(y) : "f"(x)); return y;
}
__device__ __forceinline__ float inv_ls(const float* lsp, int d) {
    float p = lsp[d];
    return 1.0f / (1e-5f + log1pf(__expf(p)));
}
__device__ __forceinline__ uint32_t smem_u32(const void* p) {
    uint32_t a;
    asm("{ .reg .u64 t; cvta.to.shared.u64 t, %1; cvt.u32.u64 %0, t; }" : "=r"(a) : "l"(p));
    return a;
}
__device__ __forceinline__ void cp_async16(uint32_t dst, const void* src) {
    asm volatile("cp.async.cg.shared.global [%0], [%1], 16;" :: "r"(dst), "l"(src));
}
__device__ __forceinline__ void cp_commit() { asm volatile("cp.async.commit_group;" ::: "memory"); }

// cvt two f32 -> packed bf16x2 (first operand = HIGH half)
__device__ __forceinline__ uint32_t cvt_bf2(float hi, float lo) {
    uint32_t r; asm("cvt.rn.bf16x2.f32 %0, %1, %2;" : "=r"(r) : "f"(hi), "f"(lo)); return r;
}
// split pair (f0 -> low lane, f1 -> high lane) into bf16 hi + residual lo
__device__ __forceinline__ void split2(float f0, float f1, uint32_t& hi, uint32_t& lo) {
    hi = cvt_bf2(f1, f0);
    float h0 = __uint_as_float(hi << 16);
    float h1 = __uint_as_float(hi & 0xffff0000u);
    lo = cvt_bf2(f1 - h1, f0 - h0);
}
__device__ __forceinline__ void mma16816(float* c, uint32_t a0, uint32_t a1,
                                         uint32_t a2, uint32_t a3,
                                         uint32_t b0, uint32_t b1) {
    asm volatile(
        "mma.sync.aligned.m16n8k16.row.col.f32.bf16.bf16.f32 "
        "{%0,%1,%2,%3}, {%4,%5,%6,%7}, {%8,%9}, {%0,%1,%2,%3};"
        : "+f"(c[0]), "+f"(c[1]), "+f"(c[2]), "+f"(c[3])
        : "r"(a0), "r"(a1), "r"(a2), "r"(a3), "r"(b0), "r"(b1));
}

// ---------- x_grid ----------
__global__ void xgrid_kernel(const float* __restrict__ tg, float* __restrict__ out) {
    int idx = blockIdx.x * blockDim.x + threadIdx.x;
    if (idx >= XG_SZ) return;
    int d = idx % DXC;
    int p = idx / DXC;
    int w = p % WWW; p /= WWW;
    int h = p % HHH; p /= HHH;
    int t = p % NTT;
    int b = p / NTT;
    float v;
    if (d == 0)      v = tg[b * NTT + t];
    else if (d == 1) v = -1.0f + (2.0f / 63.0f) * (float)h;
    else             v = -1.0f + (2.0f / 63.0f) * (float)w;
    out[idx] = v;
}

// ---------- pre: ww and sh factor tables ----------
__global__ void wwsh_kernel(const float* __restrict__ x, const float* __restrict__ lsp) {
    int idx = blockIdx.x * blockDim.x + threadIdx.x;   // 2 tables * 2b * 64 * 2048
    if (idx >= 2 * BB * 64 * NN) return;
    int n   = idx & (NN - 1);
    int r   = (idx >> 11) & 63;
    int b   = (idx >> 17) & 1;
    int tab = idx >> 18;
    int dim = tab ? 1 : 2;                             // tab0 = ww (coord 2), tab1 = sh (coord 1)
    float inv = inv_ls(lsp, dim);
    float c   = x[(b * NN + n) * 3 + dim] * inv;
    float gv  = (-1.0f + (2.0f / 63.0f) * (float)r) * inv;
    float d   = gv - c;
    float e   = ex2(-0.5f * LOG2E * d * d);
    if (tab == 0) g_ww[((size_t)b * 64 + r) * NN + n] = e;
    else          g_sh[((size_t)b * 64 + r) * NN + n] = e;
}

// ---------- pre: z_t = st*z, bf16 hi/lo, permuted for B fragments ----------
__global__ void zt_kernel(const float* __restrict__ x, const float* __restrict__ z,
                          const float* __restrict__ tg, const float* __restrict__ lsp) {
    int idx = blockIdx.x * blockDim.x + threadIdx.x;   // 2*8*16*2048 = 2^19
    if (idx >= BB * NTT * DZC * NN) return;
    int n = idx & (NN - 1);
    int e = (idx >> 11) & 15;
    int t = (idx >> 15) & 7;
    int b = idx >> 18;
    float inv0 = inv_ls(lsp, 0);
    float tv = tg[b * NTT + t] * inv0;
    float c0 = x[(b * NN + n) * 3 + 0] * inv0;
    float d  = tv - c0;
    float st = ex2(-0.5f * LOG2E * d * d);
    float v  = st * z[(b * NN + n) * DZC + e];
    __nv_bfloat16 hi = __float2bfloat16_rn(v);
    float vlo = v - __bfloat162float(hi);
    // B-fragment permutation within each 16-n group: word-pair wp -> position
    int wp  = (n >> 1) & 7;
    int pos = (wp < 4) ? (wp * 2) : ((wp - 4) * 2 + 1);
    int np  = (n & ~15) | (pos << 1) | (n & 1);
    int tgrp = t >> 1, tloc = t & 1;                   // 4 t-groups of 2
    int col  = tloc * 16 + e;                          // 0..31
    size_t o = ((size_t)(b * 4 + tgrp) * 32 + col) * NN + np;
    g_zti_hi[o] = hi;
    g_zti_lo[o] = __float2bfloat16_rn(vlo);
}

// ---------- main HMMA kernel ----------
// CTA(bid): b, tgrp(0..3), hpair. D[128 x 32] = A[128,2048] * B[32,2048]^T.
// 8 warps = 8 distinct 16-row blocks (no intra-CTA A redundancy), each warp all 32 cols.
// A row m = hl*64 + w : weight ww[b][w][n]*sh[b][h0+hl][n], in-register, bf16 hi+lo.
// 3 products: Ahi*Bhi + Ahi*Blo + Alo*Bhi.
#define KC      64
#define NCH     (NN / KC)          // 32
#define ZTHI_O  0
#define ZTLO_O  4096
#define WW_O    8192
#define SH_O    24576
#define BUFSZ   25088
#define SMEM_T  (2 * BUFSZ)        // 50176

__global__ __launch_bounds__(256, 2)
void zgrid_mma_kernel(float* __restrict__ out) {
    extern __shared__ char smem[];
    const uint32_t sb = smem_u32(smem);
    const int tid  = threadIdx.x;
    const int wid  = tid >> 5;
    const int lane = tid & 31;

    const int bid   = blockIdx.x;           // 256
    const int hpair = bid & 31;
    const int tgrp  = (bid >> 5) & 3;
    const int b     = bid >> 7;
    const int h0    = hpair * 2;
    const int b4    = b * 4 + tgrp;

    const int mbase = wid * 16;             // 16-row block per warp
    const int hl    = wid >> 2;             // 0 or 1 (sh row)
    const int mloc  = (wid & 3) * 16;       // w-row base within ww tile
    const int q8    = (lane & 3) * 8;
    const int lr    = lane >> 2;

    float acc[4][4];
#pragma unroll
    for (int j = 0; j < 4; j++)
#pragma unroll
        for (int k = 0; k < 4; k++) acc[j][k] = 0.0f;

    // ---- stage one chunk into buffer ----
    auto stage = [&](int ch) {
        const uint32_t ba = sb + (ch & 1) * BUFSZ;
        // zt hi+lo: 32 cols x 8 chunks x 2 comps = 512 x 16B
        for (int i = tid; i < 512; i += 256) {
            int comp = i >> 8;
            int r    = i & 255;
            int col  = r >> 3, c = r & 7;
            const __nv_bfloat16* src =
                (comp ? g_zti_lo : g_zti_hi) + ((size_t)b4 * 32 + col) * NN + ch * KC + c * 8;
            uint32_t dst = ba + (comp ? ZTLO_O : ZTHI_O)
                         + col * 128 + (((c >> 1) + col) & 3) * 32 + (c & 1) * 16;
            cp_async16(dst, src);
        }
        // ww: 64 rows x 16 chunks = 1024 x 16B
        for (int i = tid; i < 1024; i += 256) {
            int w = i >> 4, c = i & 15;
            const float* src = g_ww + ((size_t)b * 64 + w) * NN + ch * KC + c * 4;
            uint32_t dst = ba + WW_O + w * 256 + (((c >> 1) + w) & 7) * 32 + (c & 1) * 16;
            cp_async16(dst, src);
        }
        // sh: 2 rows x 16 x 16B
        if (tid < 32) {
            int j = tid >> 4, c = tid & 15;
            const float* src = g_sh + ((size_t)b * 64 + h0 + j) * NN + ch * KC + c * 4;
            uint32_t dst = ba + SH_O + j * 256 + c * 16;
            cp_async16(dst, src);
        }
        cp_commit();
    };

    stage(0);

    for (int ch = 0; ch < NCH; ch++) {
        if (ch + 1 < NCH) {
            stage(ch + 1);
            asm volatile("cp.async.wait_group 1;" ::: "memory");
        } else {
            asm volatile("cp.async.wait_group 0;" ::: "memory");
        }
        __syncthreads();

        const char* buf = smem + (ch & 1) * BUFSZ;

#pragma unroll
        for (int ks = 0; ks < 4; ks++) {
            // sh pairs (broadcast)
            float2 sl = *(const float2*)(buf + SH_O + hl * 256 + ks * 64 + q8);
            float2 sh = *(const float2*)(buf + SH_O + hl * 256 + ks * 64 + 32 + q8);

            int r0 = mloc + lr;
            int r1 = r0 + 8;
            float2 w0l = *(const float2*)(buf + WW_O + r0 * 256 + (((2 * ks)     + r0) & 7) * 32 + q8);
            float2 w0h = *(const float2*)(buf + WW_O + r0 * 256 + (((2 * ks + 1) + r0) & 7) * 32 + q8);
            float2 w1l = *(const float2*)(buf + WW_O + r1 * 256 + (((2 * ks)     + r1) & 7) * 32 + q8);
            float2 w1h = *(const float2*)(buf + WW_O + r1 * 256 + (((2 * ks + 1) + r1) & 7) * 32 + q8);
            uint32_t a0h, a0l, a1h, a1l, a2h, a2l, a3h, a3l;
            split2(w0l.x * sl.x, w0l.y * sl.y, a0h, a0l);  // (r0, klo)
            split2(w1l.x * sl.x, w1l.y * sl.y, a1h, a1l);  // (r1, klo)
            split2(w0h.x * sh.x, w0h.y * sh.y, a2h, a2l);  // (r0, khi)
            split2(w1h.x * sh.x, w1h.y * sh.y, a3h, a3l);  // (r1, khi)

#pragma unroll
            for (int nt = 0; nt < 4; nt++) {
                int col = nt * 8 + lr;                     // 0..31
                int off = col * 128 + ((ks + col) & 3) * 32 + q8;
                uint2 bh = *(const uint2*)(buf + ZTHI_O + off);
                uint2 bl = *(const uint2*)(buf + ZTLO_O + off);
                mma16816(acc[nt], a0h, a1h, a2h, a3h, bh.x, bh.y);
                mma16816(acc[nt], a0h, a1h, a2h, a3h, bl.x, bl.y);
                mma16816(acc[nt], a0l, a1l, a2l, a3l, bh.x, bh.y);
            }
        }
        __syncthreads();
    }

    // ---- epilogue ----
#pragma unroll
    for (int nt = 0; nt < 4; nt++) {
        int m0    = mbase + lr;                 // 0..127
        int cbase = nt * 8 + (lane & 3) * 2;    // 0..31
        int tloc  = cbase >> 4;
        int e     = cbase & 15;
        int t     = tgrp * 2 + tloc;
        int h     = h0 + (m0 >> 6);
        int w0    = m0 & 63;
        size_t i0 = (((size_t)(b * NTT + t) * HHH + h) * WWW + w0) * DZC + e;
        *(float2*)(out + i0) = make_float2(acc[nt][0], acc[nt][1]);
        size_t i1 = i0 + 8 * DZC;               // row m0+8 -> w0+8 (same h)
        *(float2*)(out + i1) = make_float2(acc[nt][2], acc[nt][3]);
    }
}

extern "C" void kernel_launch(void* const* d_in, const int* in_sizes, int n_in,
                              void* d_out, int out_size) {
    const float* x   = (const float*)d_in[0];
    const float* z   = (const float*)d_in[1];
    const float* tg  = (const float*)d_in[2];
    const float* lsp = (const float*)d_in[3];
    float* out = (float*)d_out;

    float* xg = nullptr;
    float* zg = nullptr;
    if (out_size == XG_SZ + ZG_SZ)      { xg = out; zg = out + XG_SZ; }
    else if (out_size == ZG_SZ)         { zg = out; }
    else if (out_size == XG_SZ)         { xg = out; }
    else                                { xg = out; zg = out + XG_SZ; }

    if (xg) xgrid_kernel<<<(XG_SZ + 255) / 256, 256>>>(tg, xg);
    if (zg) {
        cudaFuncSetAttribute(zgrid_mma_kernel,
                             cudaFuncAttributeMaxDynamicSharedMemorySize, SMEM_T);
        wwsh_kernel<<<(2 * BB * 64 * NN + 255) / 256, 256>>>(x, lsp);
        zt_kernel<<<(BB * NTT * DZC * NN + 255) / 256, 256>>>(x, z, tg, lsp);
        zgrid_mma_kernel<<<BB * 4 * 32, 256, SMEM_T>>>(zg);
    }
}

// round 11
// speedup vs baseline: 3.5167x; 1.0577x over previous
#include <cuda_runtime.h>
#include <cuda_bf16.h>
#include <cstdint>

// Problem constants
#define BB   2
#define NN   2048
#define NTT  8
#define HHH  64
#define WWW  64
#define DXC  3
#define DZC  16
#define GG   (NTT*HHH*WWW)
#define XG_SZ (BB*GG*DXC)         // 196608
#define ZG_SZ (BB*GG*DZC)         // 1048576
#define LOG2E 1.4426950408889634f

// ---- precomputed tables, fragment-friendly layouts ----
// ztp: per (b4,col): 8KB = 128 k16-groups x 64B; 64B = 4 quads x [b0hi b1hi b0lo b1lo]
__device__ uint8_t g_ztp[BB * 4 * 32 * 8192];   // 2 MB
// wwp/shp: per (b,row): 8KB = 128 k16-groups x 64B; 64B = 4 quads x [klo0 klo1 khi0 khi1] f32
__device__ uint8_t g_wwp[BB * 64 * 8192];       // 1 MB
__device__ uint8_t g_shp[BB * 64 * 8192];       // 1 MB

// ---------- helpers ----------
__device__ __forceinline__ float ex2(float x) {
    float y; asm("ex2.approx.ftz.f32 %0, %1;" : "=f"(y) : "f"(x)); return y;
}
__device__ __forceinline__ float inv_ls(const float* lsp, int d) {
    float p = lsp[d];
    return 1.0f / (1e-5f + log1pf(__expf(p)));
}
__device__ __forceinline__ uint32_t smem_u32(const void* p) {
    uint32_t a;
    asm("{ .reg .u64 t; cvta.to.shared.u64 t, %1; cvt.u32.u64 %0, t; }" : "=r"(a) : "l"(p));
    return a;
}
__device__ __forceinline__ void cp_async16(uint32_t dst, const void* src) {
    asm volatile("cp.async.cg.shared.global [%0], [%1], 16;" :: "r"(dst), "l"(src));
}
__device__ __forceinline__ void cp_commit() { asm volatile("cp.async.commit_group;" ::: "memory"); }

__device__ __forceinline__ uint32_t cvt_bf2(float hi, float lo) {
    uint32_t r; asm("cvt.rn.bf16x2.f32 %0, %1, %2;" : "=r"(r) : "f"(hi), "f"(lo)); return r;
}
__device__ __forceinline__ void split2(float f0, float f1, uint32_t& hi, uint32_t& lo) {
    hi = cvt_bf2(f1, f0);
    float h0 = __uint_as_float(hi << 16);
    float h1 = __uint_as_float(hi & 0xffff0000u);
    lo = cvt_bf2(f1 - h1, f0 - h0);
}
__device__ __forceinline__ void mma16816(float* c, uint32_t a0, uint32_t a1,
                                         uint32_t a2, uint32_t a3,
                                         uint32_t b0, uint32_t b1) {
    asm volatile(
        "mma.sync.aligned.m16n8k16.row.col.f32.bf16.bf16.f32 "
        "{%0,%1,%2,%3}, {%4,%5,%6,%7}, {%8,%9}, {%0,%1,%2,%3};"
        : "+f"(c[0]), "+f"(c[1]), "+f"(c[2]), "+f"(c[3])
        : "r"(a0), "r"(a1), "r"(a2), "r"(a3), "r"(b0), "r"(b1));
}

// ---------- fused prep kernel: xgrid + ww/sh tables + zt tables ----------
#define WWSH_N (2 * BB * 64 * NN)        // 524288
#define ZT_N   (BB * NTT * DZC * NN)     // 524288
#define PREP_N (XG_SZ + WWSH_N + ZT_N)   // 1245184

__global__ void prep_kernel(const float* __restrict__ x, const float* __restrict__ z,
                            const float* __restrict__ tg, const float* __restrict__ lsp,
                            float* __restrict__ xg) {
    int idx = blockIdx.x * blockDim.x + threadIdx.x;
    if (idx < XG_SZ) {
        if (xg) {
            int d = idx % DXC;
            int p = idx / DXC;
            int w = p % WWW; p /= WWW;
            int h = p % HHH; p /= HHH;
            int t = p % NTT;
            int b = p / NTT;
            float v;
            if (d == 0)      v = tg[b * NTT + t];
            else if (d == 1) v = -1.0f + (2.0f / 63.0f) * (float)h;
            else             v = -1.0f + (2.0f / 63.0f) * (float)w;
            xg[idx] = v;
        }
        return;
    }
    idx -= XG_SZ;
    if (idx < WWSH_N) {
        int n   = idx & (NN - 1);
        int r   = (idx >> 11) & 63;
        int b   = (idx >> 17) & 1;
        int tab = idx >> 18;
        int dim = tab ? 1 : 2;                      // tab0 = ww (coord 2), tab1 = sh (coord 1)
        float inv = inv_ls(lsp, dim);
        float c   = x[(b * NN + n) * 3 + dim] * inv;
        float gv  = (-1.0f + (2.0f / 63.0f) * (float)r) * inv;
        float d   = gv - c;
        float e   = ex2(-0.5f * LOG2E * d * d);
        int q = (n & 7) >> 1, half = (n >> 3) & 1, byt = n & 1, ksg = n >> 4;
        size_t off = ((size_t)(b * 64 + r) << 13) + ksg * 64 + q * 16 + half * 8 + byt * 4;
        *(float*)((tab ? g_shp : g_wwp) + off) = e;
        return;
    }
    idx -= WWSH_N;
    {
        int n = idx & (NN - 1);
        int e = (idx >> 11) & 15;
        int t = (idx >> 15) & 7;
        int b = idx >> 18;
        float inv0 = inv_ls(lsp, 0);
        float tv = tg[b * NTT + t] * inv0;
        float c0 = x[(b * NN + n) * 3 + 0] * inv0;
        float d  = tv - c0;
        float st = ex2(-0.5f * LOG2E * d * d);
        float v  = st * z[(b * NN + n) * DZC + e];
        __nv_bfloat16 hi = __float2bfloat16_rn(v);
        float vlo = v - __bfloat162float(hi);
        int tgrp = t >> 1, tloc = t & 1;
        int col  = tloc * 16 + e;
        int b4   = b * 4 + tgrp;
        int q = (n & 7) >> 1, half = (n >> 3) & 1, byt = n & 1, ksg = n >> 4;
        size_t base = ((size_t)(b4 * 32 + col) << 13) + ksg * 64 + q * 16 + half * 4 + byt * 2;
        *(__nv_bfloat16*)(g_ztp + base)     = hi;                       // hi at +0
        *(__nv_bfloat16*)(g_ztp + base + 8) = __float2bfloat16_rn(vlo); // lo at +8
    }
}

// ---------- main HMMA kernel ----------
// CTA(bid): b, tgrp(0..3), hpair. D[128 x 32] = A[128,2048] * B[32,2048]^T.
// 8 warps = 8 distinct 16-row blocks; each warp all 32 cols.
// 3 products: Ahi*Bhi + Ahi*Blo + Alo*Bhi.
#define KC      128
#define NCH     (NN / KC)          // 16
#define ZT_O    0                  // 16 KB: 32 cols x 512B
#define WW_O    16384              // 32 KB: 64 rows x 512B
#define SH_O    49152              // 1 KB : 2 rows x 512B
#define BUFSZ   50176
#define SMEM_T  (2 * BUFSZ)        // 100352

__global__ __launch_bounds__(256, 2)
void zgrid_mma_kernel(float* __restrict__ out) {
    extern __shared__ char smem[];
    const uint32_t sb = smem_u32(smem);
    const int tid  = threadIdx.x;
    const int wid  = tid >> 5;
    const int lane = tid & 31;

    const int bid   = blockIdx.x;           // 256
    const int hpair = bid & 31;
    const int tgrp  = (bid >> 5) & 3;
    const int b     = bid >> 7;
    const int h0    = hpair * 2;
    const int b4    = b * 4 + tgrp;

    const int mbase = wid * 16;             // warp's 16-row block
    const int hl    = wid >> 2;             // sh row (0/1)
    const int mloc  = (wid & 3) * 16;       // ww row base
    const int q16   = (lane & 3) * 16;
    const int lr    = lane >> 2;

    float acc[4][4];
#pragma unroll
    for (int j = 0; j < 4; j++)
#pragma unroll
        for (int k = 0; k < 4; k++) acc[j][k] = 0.0f;

    auto stage = [&](int ch) {
        const uint32_t ba = sb + (ch & 1) * BUFSZ;
        // zt: 32 cols x 32 x 16B
        for (int i = tid; i < 1024; i += 256) {
            int col = i >> 5, u = i & 31, ksl = u >> 2, sub = u & 3;
            const uint8_t* src = g_ztp + ((size_t)(b4 * 32 + col) << 13)
                               + (ch * 8 + ksl) * 64 + sub * 16;
            uint32_t dst = ba + ZT_O + col * 512 + ((ksl + col) & 7) * 64 + sub * 16;
            cp_async16(dst, src);
        }
        // ww: 64 rows x 32 x 16B
        for (int i = tid; i < 2048; i += 256) {
            int r = i >> 5, u = i & 31, ksl = u >> 2, sub = u & 3;
            const uint8_t* src = g_wwp + ((size_t)(b * 64 + r) << 13)
                               + (ch * 8 + ksl) * 64 + sub * 16;
            uint32_t dst = ba + WW_O + r * 512 + ((ksl + r) & 7) * 64 + sub * 16;
            cp_async16(dst, src);
        }
        // sh: 2 rows x 32 x 16B
        if (tid < 64) {
            int j = tid >> 5, u = tid & 31, ksl = u >> 2, sub = u & 3;
            const uint8_t* src = g_shp + ((size_t)(b * 64 + h0 + j) << 13)
                               + (ch * 8 + ksl) * 64 + sub * 16;
            uint32_t dst = ba + SH_O + j * 512 + ksl * 64 + sub * 16;
            cp_async16(dst, src);
        }
        cp_commit();
    };

    stage(0);

    const int r0 = mloc + lr;
    const int r1 = r0 + 8;

    for (int ch = 0; ch < NCH; ch++) {
        if (ch + 1 < NCH) {
            stage(ch + 1);
            asm volatile("cp.async.wait_group 1;" ::: "memory");
        } else {
            asm volatile("cp.async.wait_group 0;" ::: "memory");
        }
        __syncthreads();

        const char* buf = smem + (ch & 1) * BUFSZ;

#pragma unroll
        for (int ks = 0; ks < 8; ks++) {
            float4 s  = *(const float4*)(buf + SH_O + hl * 512 + ks * 64 + q16);
            float4 w0 = *(const float4*)(buf + WW_O + r0 * 512 + ((ks + r0) & 7) * 64 + q16);
            float4 w1 = *(const float4*)(buf + WW_O + r1 * 512 + ((ks + r1) & 7) * 64 + q16);
            uint32_t a0h, a0l, a1h, a1l, a2h, a2l, a3h, a3l;
            split2(w0.x * s.x, w0.y * s.y, a0h, a0l);   // (r0, klo)
            split2(w1.x * s.x, w1.y * s.y, a1h, a1l);   // (r1, klo)
            split2(w0.z * s.z, w0.w * s.w, a2h, a2l);   // (r0, khi)
            split2(w1.z * s.z, w1.w * s.w, a3h, a3l);   // (r1, khi)

#pragma unroll
            for (int nt = 0; nt < 4; nt++) {
                int col = nt * 8 + lr;
                uint4 bb = *(const uint4*)(buf + ZT_O + col * 512 + ((ks + col) & 7) * 64 + q16);
                mma16816(acc[nt], a0h, a1h, a2h, a3h, bb.x, bb.y);
                mma16816(acc[nt], a0h, a1h, a2h, a3h, bb.z, bb.w);
                mma16816(acc[nt], a0l, a1l, a2l, a3l, bb.x, bb.y);
            }
        }
        __syncthreads();
    }

    // ---- epilogue ----
#pragma unroll
    for (int nt = 0; nt < 4; nt++) {
        int m0    = mbase + lr;                 // 0..127
        int cbase = nt * 8 + (lane & 3) * 2;    // 0..31
        int tloc  = cbase >> 4;
        int e     = cbase & 15;
        int t     = tgrp * 2 + tloc;
        int h     = h0 + (m0 >> 6);
        int w0    = m0 & 63;
        size_t i0 = (((size_t)(b * NTT + t) * HHH + h) * WWW + w0) * DZC + e;
        *(float2*)(out + i0) = make_float2(acc[nt][0], acc[nt][1]);
        size_t i1 = i0 + 8 * DZC;               // row m0+8 -> w0+8 (same h)
        *(float2*)(out + i1) = make_float2(acc[nt][2], acc[nt][3]);
    }
}

extern "C" void kernel_launch(void* const* d_in, const int* in_sizes, int n_in,
                              void* d_out, int out_size) {
    const float* x   = (const float*)d_in[0];
    const float* z   = (const float*)d_in[1];
    const float* tg  = (const float*)d_in[2];
    const float* lsp = (const float*)d_in[3];
    float* out = (float*)d_out;

    float* xg = nullptr;
    float* zg = nullptr;
    if (out_size == XG_SZ + ZG_SZ)      { xg = out; zg = out + XG_SZ; }
    else if (out_size == ZG_SZ)         { zg = out; }
    else if (out_size == XG_SZ)         { xg = out; }
    else                                { xg = out; zg = out + XG_SZ; }

    prep_kernel<<<(PREP_N + 255) / 256, 256>>>(x, z, tg, lsp, xg);
    if (zg) {
        cudaFuncSetAttribute(zgrid_mma_kernel,
                             cudaFuncAttributeMaxDynamicSharedMemorySize, SMEM_T);
        zgrid_mma_kernel<<<BB * 4 * 32, 256, SMEM_T>>>(zg);
    }
}

// round 12
// speedup vs baseline: 3.5508x; 1.0097x over previous
#include <cuda_runtime.h>
#include <cuda_bf16.h>
#include <cstdint>

// Problem constants
#define BB   2
#define NN   2048
#define NTT  8
#define HHH  64
#define WWW  64
#define DXC  3
#define DZC  16
#define GG   (NTT*HHH*WWW)
#define XG_SZ (BB*GG*DXC)         // 196608
#define ZG_SZ (BB*GG*DZC)         // 1048576
#define LOG2E 1.4426950408889634f

// ---- precomputed tables, fragment-friendly layouts ----
// ztp: per (b4,col): 8KB = 128 k16-groups x 64B; 64B = 4 quads x [b0hi b1hi b0lo b1lo]
__device__ uint8_t g_ztp[BB * 4 * 32 * 8192];   // 2 MB
// wwp/shp: per (b,row): 8KB = 128 k16-groups x 64B; 64B = 4 quads x [klo0 klo1 khi0 khi1] f32
__device__ uint8_t g_wwp[BB * 64 * 8192];       // 1 MB
__device__ uint8_t g_shp[BB * 64 * 8192];       // 1 MB

// ---------- helpers ----------
__device__ __forceinline__ float ex2(float x) {
    float y; asm("ex2.approx.ftz.f32 %0, %1;" : "=f"(y) : "f"(x)); return y;
}
__device__ __forceinline__ float inv_ls(const float* lsp, int d) {
    float p = lsp[d];
    return 1.0f / (1e-5f + log1pf(__expf(p)));
}
__device__ __forceinline__ uint32_t smem_u32(const void* p) {
    uint32_t a;
    asm("{ .reg .u64 t; cvta.to.shared.u64 t, %1; cvt.u32.u64 %0, t; }" : "=r"(a) : "l"(p));
    return a;
}
__device__ __forceinline__ void cp_async16(uint32_t dst, const void* src) {
    asm volatile("cp.async.cg.shared.global [%0], [%1], 16;" :: "r"(dst), "l"(src));
}
__device__ __forceinline__ void cp_commit() { asm volatile("cp.async.commit_group;" ::: "memory"); }

__device__ __forceinline__ uint32_t cvt_bf2(float hi, float lo) {
    uint32_t r; asm("cvt.rn.bf16x2.f32 %0, %1, %2;" : "=r"(r) : "f"(hi), "f"(lo)); return r;
}
__device__ __forceinline__ void split2(float f0, float f1, uint32_t& hi, uint32_t& lo) {
    hi = cvt_bf2(f1, f0);
    float h0 = __uint_as_float(hi << 16);
    float h1 = __uint_as_float(hi & 0xffff0000u);
    lo = cvt_bf2(f1 - h1, f0 - h0);
}
__device__ __forceinline__ void mma16816(float* c, uint32_t a0, uint32_t a1,
                                         uint32_t a2, uint32_t a3,
                                         uint32_t b0, uint32_t b1) {
    asm volatile(
        "mma.sync.aligned.m16n8k16.row.col.f32.bf16.bf16.f32 "
        "{%0,%1,%2,%3}, {%4,%5,%6,%7}, {%8,%9}, {%0,%1,%2,%3};"
        : "+f"(c[0]), "+f"(c[1]), "+f"(c[2]), "+f"(c[3])
        : "r"(a0), "r"(a1), "r"(a2), "r"(a3), "r"(b0), "r"(b1));
}

// ---------- fused prep kernel: xgrid + ww/sh tables + zt tables ----------
#define WWSH_N (2 * BB * 64 * NN)        // 524288
#define ZT_N   (BB * NTT * DZC * NN)     // 524288
#define PREP_N (XG_SZ + WWSH_N + ZT_N)   // 1245184

__global__ void prep_kernel(const float* __restrict__ x, const float* __restrict__ z,
                            const float* __restrict__ tg, const float* __restrict__ lsp,
                            float* __restrict__ xg) {
    int idx = blockIdx.x * blockDim.x + threadIdx.x;
    if (idx < XG_SZ) {
        if (xg) {
            int d = idx % DXC;
            int p = idx / DXC;
            int w = p % WWW; p /= WWW;
            int h = p % HHH; p /= HHH;
            int t = p % NTT;
            int b = p / NTT;
            float v;
            if (d == 0)      v = tg[b * NTT + t];
            else if (d == 1) v = -1.0f + (2.0f / 63.0f) * (float)h;
            else             v = -1.0f + (2.0f / 63.0f) * (float)w;
            xg[idx] = v;
        }
        return;
    }
    idx -= XG_SZ;
    if (idx < WWSH_N) {
        int n   = idx & (NN - 1);
        int r   = (idx >> 11) & 63;
        int b   = (idx >> 17) & 1;
        int tab = idx >> 18;
        int dim = tab ? 1 : 2;                      // tab0 = ww (coord 2), tab1 = sh (coord 1)
        float inv = inv_ls(lsp, dim);
        float c   = x[(b * NN + n) * 3 + dim] * inv;
        float gv  = (-1.0f + (2.0f / 63.0f) * (float)r) * inv;
        float d   = gv - c;
        float e   = ex2(-0.5f * LOG2E * d * d);
        int q = (n & 7) >> 1, half = (n >> 3) & 1, byt = n & 1, ksg = n >> 4;
        size_t off = ((size_t)(b * 64 + r) << 13) + ksg * 64 + q * 16 + half * 8 + byt * 4;
        *(float*)((tab ? g_shp : g_wwp) + off) = e;
        return;
    }
    idx -= WWSH_N;
    {
        int n = idx & (NN - 1);
        int e = (idx >> 11) & 15;
        int t = (idx >> 15) & 7;
        int b = idx >> 18;
        float inv0 = inv_ls(lsp, 0);
        float tv = tg[b * NTT + t] * inv0;
        float c0 = x[(b * NN + n) * 3 + 0] * inv0;
        float d  = tv - c0;
        float st = ex2(-0.5f * LOG2E * d * d);
        float v  = st * z[(b * NN + n) * DZC + e];
        __nv_bfloat16 hi = __float2bfloat16_rn(v);
        float vlo = v - __bfloat162float(hi);
        int tgrp = t >> 1, tloc = t & 1;
        int col  = tloc * 16 + e;
        int b4   = b * 4 + tgrp;
        int q = (n & 7) >> 1, half = (n >> 3) & 1, byt = n & 1, ksg = n >> 4;
        size_t base = ((size_t)(b4 * 32 + col) << 13) + ksg * 64 + q * 16 + half * 4 + byt * 2;
        *(__nv_bfloat16*)(g_ztp + base)     = hi;                       // hi at +0
        *(__nv_bfloat16*)(g_ztp + base + 8) = __float2bfloat16_rn(vlo); // lo at +8
    }
}

// ---------- main HMMA kernel ----------
// CTA(bid): b, tgrp(0..3), hpair. D[128 x 32] = A[128,2048] * B[32,2048]^T.
// 8 warps = 8 distinct 16-row blocks; each warp all 32 cols.
// 3 products: Ahi*Bhi + Ahi*Blo + Alo*Bhi.
#define KC      128
#define NCH     (NN / KC)          // 16
#define ZT_O    0                  // 16 KB: 32 cols x 512B
#define WW_O    16384              // 32 KB: 64 rows x 512B
#define SH_O    49152              // 1 KB : 2 rows x 512B
#define BUFSZ   50176
#define SMEM_T  (2 * BUFSZ)        // 100352

__global__ __launch_bounds__(256, 2)
void zgrid_mma_kernel(float* __restrict__ out) {
    extern __shared__ char smem[];
    const uint32_t sb = smem_u32(smem);
    const int tid  = threadIdx.x;
    const int wid  = tid >> 5;
    const int lane = tid & 31;

    const int bid   = blockIdx.x;           // 256
    const int hpair = bid & 31;
    const int tgrp  = (bid >> 5) & 3;
    const int b     = bid >> 7;
    const int h0    = hpair * 2;
    const int b4    = b * 4 + tgrp;

    const int mbase = wid * 16;             // warp's 16-row block
    const int hl    = wid >> 2;             // sh row (0/1)
    const int mloc  = (wid & 3) * 16;       // ww row base
    const int q16   = (lane & 3) * 16;
    const int lr    = lane >> 2;

    float acc[4][4];
#pragma unroll
    for (int j = 0; j < 4; j++)
#pragma unroll
        for (int k = 0; k < 4; k++) acc[j][k] = 0.0f;

    auto stage = [&](int ch) {
        const uint32_t ba = sb + (ch & 1) * BUFSZ;
        // zt: 32 cols x 32 x 16B
        for (int i = tid; i < 1024; i += 256) {
            int col = i >> 5, u = i & 31, ksl = u >> 2, sub = u & 3;
            const uint8_t* src = g_ztp + ((size_t)(b4 * 32 + col) << 13)
                               + (ch * 8 + ksl) * 64 + sub * 16;
            uint32_t dst = ba + ZT_O + col * 512 + ((ksl + col) & 7) * 64 + sub * 16;
            cp_async16(dst, src);
        }
        // ww: 64 rows x 32 x 16B
        for (int i = tid; i < 2048; i += 256) {
            int r = i >> 5, u = i & 31, ksl = u >> 2, sub = u & 3;
            const uint8_t* src = g_wwp + ((size_t)(b * 64 + r) << 13)
                               + (ch * 8 + ksl) * 64 + sub * 16;
            uint32_t dst = ba + WW_O + r * 512 + ((ksl + r) & 7) * 64 + sub * 16;
            cp_async16(dst, src);
        }
        // sh: 2 rows x 32 x 16B
        if (tid < 64) {
            int j = tid >> 5, u = tid & 31, ksl = u >> 2, sub = u & 3;
            const uint8_t* src = g_shp + ((size_t)(b * 64 + h0 + j) << 13)
                               + (ch * 8 + ksl) * 64 + sub * 16;
            uint32_t dst = ba + SH_O + j * 512 + ksl * 64 + sub * 16;
            cp_async16(dst, src);
        }
        cp_commit();
    };

    stage(0);

    const int r0 = mloc + lr;
    const int r1 = r0 + 8;

    for (int ch = 0; ch < NCH; ch++) {
        if (ch + 1 < NCH) {
            stage(ch + 1);
            asm volatile("cp.async.wait_group 1;" ::: "memory");
        } else {
            asm volatile("cp.async.wait_group 0;" ::: "memory");
        }
        __syncthreads();

        const char* buf = smem + (ch & 1) * BUFSZ;

#pragma unroll
        for (int ks = 0; ks < 8; ks++) {
            float4 s  = *(const float4*)(buf + SH_O + hl * 512 + ks * 64 + q16);
            float4 w0 = *(const float4*)(buf + WW_O + r0 * 512 + ((ks + r0) & 7) * 64 + q16);
            float4 w1 = *(const float4*)(buf + WW_O + r1 * 512 + ((ks + r1) & 7) * 64 + q16);
            uint32_t a0h, a0l, a1h, a1l, a2h, a2l, a3h, a3l;
            split2(w0.x * s.x, w0.y * s.y, a0h, a0l);   // (r0, klo)
            split2(w1.x * s.x, w1.y * s.y, a1h, a1l);   // (r1, klo)
            split2(w0.z * s.z, w0.w * s.w, a2h, a2l);   // (r0, khi)
            split2(w1.z * s.z, w1.w * s.w, a3h, a3l);   // (r1, khi)

#pragma unroll
            for (int nt = 0; nt < 4; nt++) {
                int col = nt * 8 + lr;
                uint4 bb = *(const uint4*)(buf + ZT_O + col * 512 + ((ks + col) & 7) * 64 + q16);
                mma16816(acc[nt], a0h, a1h, a2h, a3h, bb.x, bb.y);
                mma16816(acc[nt], a0h, a1h, a2h, a3h, bb.z, bb.w);
                mma16816(acc[nt], a0l, a1l, a2l, a3l, bb.x, bb.y);
            }
        }
        __syncthreads();
    }

    // ---- epilogue ----
#pragma unroll
    for (int nt = 0; nt < 4; nt++) {
        int m0    = mbase + lr;                 // 0..127
        int cbase = nt * 8 + (lane & 3) * 2;    // 0..31
        int tloc  = cbase >> 4;
        int e     = cbase & 15;
        int t     = tgrp * 2 + tloc;
        int h     = h0 + (m0 >> 6);
        int w0    = m0 & 63;
        size_t i0 = (((size_t)(b * NTT + t) * HHH + h) * WWW + w0) * DZC + e;
        *(float2*)(out + i0) = make_float2(acc[nt][0], acc[nt][1]);
        size_t i1 = i0 + 8 * DZC;               // row m0+8 -> w0+8 (same h)
        *(float2*)(out + i1) = make_float2(acc[nt][2], acc[nt][3]);
    }
}

extern "C" void kernel_launch(void* const* d_in, const int* in_sizes, int n_in,
                              void* d_out, int out_size) {
    const float* x   = (const float*)d_in[0];
    const float* z   = (const float*)d_in[1];
    const float* tg  = (const float*)d_in[2];
    const float* lsp = (const float*)d_in[3];
    float* out = (float*)d_out;

    float* xg = nullptr;
    float* zg = nullptr;
    if (out_size == XG_SZ + ZG_SZ)      { xg = out; zg = out + XG_SZ; }
    else if (out_size == ZG_SZ)         { zg = out; }
    else if (out_size == XG_SZ)         { xg = out; }
    else                                { xg = out; zg = out + XG_SZ; }

    prep_kernel<<<(PREP_N + 255) / 256, 256>>>(x, z, tg, lsp, xg);
    if (zg) {
        cudaFuncSetAttribute(zgrid_mma_kernel,
                             cudaFuncAttributeMaxDynamicSharedMemorySize, SMEM_T);
        zgrid_mma_kernel<<<BB * 4 * 32, 256, SMEM_T>>>(zg);
    }
}